// round 3
// baseline (speedup 1.0000x reference)
#include <cuda_runtime.h>

#define GRID9   9
#define SN      81          // STATE_NUM
#define HID     32
#define WARPS   4
#define THREADS (WARPS * 32)
#define BANDW   19          // band elements per row: offsets -9..+9 around 82j
#define BPITCH  21          // padded (odd -> conflict-free strided access)
#define NELEMS  (SN * SN)   // 6561
#define BAND_TOT (SN * BANDW)  // 1539

__global__ __launch_bounds__(THREADS)
void gdvpn_kernel(const float* __restrict__ obs,     // (B, 2*SN)
                  const float* __restrict__ A,       // (B, SN, SN)
                  const float* __restrict__ W1,      // (SN, HID)
                  const float* __restrict__ W2,      // (HID, HID)
                  const float* __restrict__ W3,      // (HID, 1)
                  const float* __restrict__ b3,      // (1,)
                  float* __restrict__ out,           // [sym B | ir B | nr B | nsc B*SN]
                  int B)
{
    __shared__ float sW1[SN * HID];            // 10368 B
    __shared__ float sW2[HID * HID];           //  4096 B
    __shared__ float sW3[HID];                 //   128 B
    __shared__ float sBand[WARPS][SN * BPITCH];// 4 * 6804 B
    __shared__ float sNsc[WARPS][84];          // padded
    __shared__ float sH1[WARPS][HID];

    const int tid = threadIdx.x;
    for (int k = tid; k < SN * HID; k += THREADS) sW1[k] = W1[k];
    for (int k = tid; k < HID * HID; k += THREADS) sW2[k] = W2[k];
    if (tid < HID) sW3[tid] = W3[tid];
    __syncthreads();

    const int warp = tid >> 5;
    const int lane = tid & 31;
    const int b = blockIdx.x * WARPS + warp;
    if (b >= B) return;

    const float* __restrict__ Ab  = A + (size_t)b * NELEMS;
    const float* __restrict__ dem = obs + (size_t)b * (2 * SN) + SN;
    float* __restrict__ band = sBand[warp];

    // ------- Phase 0: coalesced band staging -------
    // For row j, copy A-flat[82j-9 .. 82j+9] -> band[j*21 + 0..18].
    // Lane walks idx = lane, lane+32, ... over the 81*19 virtual band;
    // consecutive lanes hit consecutive global addresses (fully coalesced).
    {
        int row = (lane >= BANDW) ? 1 : 0;
        int off = lane - row * BANDW;
        #pragma unroll 1
        for (int idx = lane; idx < BAND_TOT; idx += 32) {
            const int e = 82 * row + off - 9;          // flat index into A
            float v = 0.0f;
            if ((unsigned)e <= (unsigned)(NELEMS - 1)) v = __ldg(&Ab[e]);
            band[row * BPITCH + off] = v;
            // advance (row, off) by 32 band slots
            off += 32;
            if (off >= 2 * BANDW) { off -= 2 * BANDW; row += 2; }
            else                  { off -= BANDW;     row += 1; }
        }
    }
    __syncwarp();

    // ------- Phase 1: nsc from band + immediate reward -------
    // nsc[i] = band[i][9] + (c>0)band[i-1][10] + (c<8)band[i+1][8]
    //        + (r>0)band[i-9][18] + (r<8)band[i+9][0]
    float ir = 0.0f;
    #pragma unroll
    for (int t = 0; t < 3; ++t) {
        const int i = lane + 32 * t;
        if (i < SN) {
            const int r = i / GRID9;
            const int c = i - r * GRID9;
            float v = band[i * BPITCH + 9];
            if (c > 0)         v += band[(i - 1) * BPITCH + 10];
            if (c < GRID9 - 1) v += band[(i + 1) * BPITCH + 8];
            if (r > 0)         v += band[(i - GRID9) * BPITCH + 18];
            if (r < GRID9 - 1) v += band[(i + GRID9) * BPITCH + 0];
            ir += fminf(v, __ldg(&dem[i]));
            sNsc[warp][i] = v;
            out[(size_t)3 * B + (size_t)b * SN + i] = v;   // nsc output
        }
    }
    #pragma unroll
    for (int off = 16; off; off >>= 1) ir += __shfl_xor_sync(0xffffffffu, ir, off);
    __syncwarp();

    // ------- Phase 2: h1 = relu(nsc @ W1); lane owns hidden unit `lane` -------
    float h1 = 0.0f;
    #pragma unroll 3
    for (int i = 0; i < SN; ++i)
        h1 = fmaf(sNsc[warp][i], sW1[i * HID + lane], h1);
    h1 = fmaxf(h1, 0.0f);
    sH1[warp][lane] = h1;
    __syncwarp();

    // ------- Phase 3: h2 = relu(h1 @ W2); next_return = h2 @ W3 + b3 -------
    float h2 = 0.0f;
    #pragma unroll
    for (int k = 0; k < HID; ++k)
        h2 = fmaf(sH1[warp][k], sW2[k * HID + lane], h2);
    h2 = fmaxf(h2, 0.0f);

    float nr = h2 * sW3[lane];
    #pragma unroll
    for (int off = 16; off; off >>= 1) nr += __shfl_xor_sync(0xffffffffu, nr, off);

    if (lane == 0) {
        nr += __ldg(&b3[0]);
        out[b]                 = ir + nr;   // symbolic_val
        out[(size_t)B + b]     = ir;        // immediate_reward
        out[(size_t)2 * B + b] = nr;        // next_return
    }
}

extern "C" void kernel_launch(void* const* d_in, const int* in_sizes, int n_in,
                              void* d_out, int out_size)
{
    const float* obs = (const float*)d_in[0];
    const float* A   = (const float*)d_in[1];
    const float* W1  = (const float*)d_in[2];
    const float* W2  = (const float*)d_in[3];
    const float* W3  = (const float*)d_in[4];
    const float* b3  = (const float*)d_in[5];

    const int B = in_sizes[0] / (2 * SN);
    float* out = (float*)d_out;

    const int blocks = (B + WARPS - 1) / WARPS;
    gdvpn_kernel<<<blocks, THREADS>>>(obs, A, W1, W2, W3, b3, out, B);
}

// round 5
// speedup vs baseline: 2.6119x; 2.6119x over previous
#include <cuda_runtime.h>

#define GRID9   9
#define SN      81
#define HID     32
#define NELEMS  (SN * SN)     // 6561
#define BANDW   19            // band offsets -9..+9 around 82j
#define BPITCH  21            // odd pitch -> conflict-free

// ======================= Kernel 1: streaming nsc =======================
// One block (128 threads) per batch. Coalesced band load -> smem -> nsc.
__global__ __launch_bounds__(128)
void nsc_kernel(const float* __restrict__ obs,   // (B, 2*SN)
                const float* __restrict__ A,     // (B, SN, SN)
                float* __restrict__ out,         // [sym|ir|nr|nsc]
                int B)
{
    __shared__ float band[SN * BPITCH];   // 6804 B
    __shared__ float sIr[4];

    const int b    = blockIdx.x;
    const int warp = threadIdx.x >> 5;
    const int lane = threadIdx.x & 31;
    const int i    = threadIdx.x;         // state index this thread owns
    const float* __restrict__ Ab = A + (size_t)b * NELEMS;

    // Early demand load: overlaps with band staging + barrier.
    float dem = 0.0f;
    if (i < SN) dem = __ldg(&obs[(size_t)b * (2 * SN) + SN + i]);

    // Band staging: warp w handles rows w, w+4, ... (21 unrolled iters).
    // Row j: lanes 0..18 load the contiguous segment A[82j-9 .. 82j+9].
    const bool ld = (lane < BANDW);
    #pragma unroll
    for (int t = 0; t < 21; ++t) {
        const int j = warp + 4 * t;
        if (j < SN && ld) {
            const int e = 82 * j - 9 + lane;
            float v = 0.0f;
            if ((unsigned)e < (unsigned)NELEMS) v = __ldg(&Ab[e]);
            band[j * BPITCH + lane] = v;
        }
    }
    __syncthreads();

    // nsc[i] = band[i][9] + (c>0)band[i-1][10] + (c<8)band[i+1][8]
    //        + (r>0)band[i-9][18] + (r<8)band[i+9][0]
    float m = 0.0f;
    if (i < SN) {
        const int r = i / GRID9;
        const int c = i - r * GRID9;
        float v = band[i * BPITCH + 9];
        if (c > 0)         v += band[(i - 1) * BPITCH + 10];
        if (c < GRID9 - 1) v += band[(i + 1) * BPITCH + 8];
        if (r > 0)         v += band[(i - GRID9) * BPITCH + 18];
        if (r < GRID9 - 1) v += band[(i + GRID9) * BPITCH + 0];
        out[(size_t)3 * B + (size_t)b * SN + i] = v;   // nsc
        m = fminf(v, dem);                              // served
    }
    #pragma unroll
    for (int off = 16; off; off >>= 1) m += __shfl_xor_sync(0xffffffffu, m, off);
    if (lane == 0) sIr[warp] = m;
    __syncthreads();
    if (threadIdx.x == 0)
        out[(size_t)B + b] = sIr[0] + sIr[1] + sIr[2] + sIr[3];    // immediate_reward
}

// ======================= Kernel 2: MLP head =======================
// Warp per batch, 8 warps/block, weights staged once per block.
#define WARPS2   8
#define THREADS2 (WARPS2 * 32)

__global__ __launch_bounds__(THREADS2)
void mlp_kernel(const float* __restrict__ W1,    // (SN, HID)
                const float* __restrict__ W2,    // (HID, HID)
                const float* __restrict__ W3,    // (HID, 1)
                const float* __restrict__ b3,
                float* __restrict__ out,         // [sym|ir|nr|nsc]
                int B)
{
    __shared__ float sW1[SN * HID];
    __shared__ float sW2[HID * HID];
    __shared__ float sW3[HID];
    __shared__ float sNsc[WARPS2][84];
    __shared__ float sH1[WARPS2][HID];

    const int tid = threadIdx.x;
    for (int k = tid; k < SN * HID; k += THREADS2) sW1[k] = W1[k];
    for (int k = tid; k < HID * HID; k += THREADS2) sW2[k] = W2[k];
    if (tid < HID) sW3[tid] = W3[tid];
    __syncthreads();

    const int warp = tid >> 5;
    const int lane = tid & 31;
    const int b = blockIdx.x * WARPS2 + warp;
    if (b >= B) return;

    const float* __restrict__ nscRow = out + (size_t)3 * B + (size_t)b * SN;
    #pragma unroll
    for (int t = 0; t < 3; ++t) {
        const int i = lane + 32 * t;
        if (i < SN) sNsc[warp][i] = __ldg(&nscRow[i]);
    }
    __syncwarp();

    // h1 = relu(nsc @ W1); lane owns hidden unit `lane`
    float h1 = 0.0f;
    #pragma unroll 3
    for (int i = 0; i < SN; ++i)
        h1 = fmaf(sNsc[warp][i], sW1[i * HID + lane], h1);
    h1 = fmaxf(h1, 0.0f);
    sH1[warp][lane] = h1;
    __syncwarp();

    // h2 = relu(h1 @ W2); nr = h2 @ W3 + b3
    float h2 = 0.0f;
    #pragma unroll
    for (int k = 0; k < HID; ++k)
        h2 = fmaf(sH1[warp][k], sW2[k * HID + lane], h2);
    h2 = fmaxf(h2, 0.0f);

    float nr = h2 * sW3[lane];
    #pragma unroll
    for (int off = 16; off; off >>= 1) nr += __shfl_xor_sync(0xffffffffu, nr, off);

    if (lane == 0) {
        nr += __ldg(&b3[0]);
        const float ir = out[(size_t)B + b];   // written by nsc_kernel (L2-hot)
        out[b]                 = ir + nr;      // symbolic_val
        out[(size_t)2 * B + b] = nr;           // next_return
    }
}

extern "C" void kernel_launch(void* const* d_in, const int* in_sizes, int n_in,
                              void* d_out, int out_size)
{
    const float* obs = (const float*)d_in[0];
    const float* A   = (const float*)d_in[1];
    const float* W1  = (const float*)d_in[2];
    const float* W2  = (const float*)d_in[3];
    const float* W3  = (const float*)d_in[4];
    const float* b3  = (const float*)d_in[5];

    const int B = in_sizes[0] / (2 * SN);
    float* out = (float*)d_out;

    nsc_kernel<<<B, 128>>>(obs, A, out, B);
    mlp_kernel<<<(B + WARPS2 - 1) / WARPS2, THREADS2>>>(W1, W2, W3, b3, out, B);
}

// round 6
// speedup vs baseline: 2.7731x; 1.0617x over previous
#include <cuda_runtime.h>

#define GRID9   9
#define SN      81
#define HID     32
#define NELEMS  (SN * SN)        // 6561
#define BANDW   19               // band offsets -9..+9 around 82j
#define BPITCH  21               // odd pitch -> conflict-free
#define BAND_TOT (SN * BANDW)    // 1539

// ======================= Kernel 1: streaming nsc =======================
// One block (128 threads) per batch. Flattened full-lane coalesced band load.
__global__ __launch_bounds__(128)
void nsc_kernel(const float* __restrict__ obs,   // (B, 2*SN)
                const float* __restrict__ A,     // (B, SN, SN)
                float* __restrict__ out,         // [sym|ir|nr|nsc]
                int B)
{
    __shared__ float band[SN * BPITCH];   // 6804 B
    __shared__ float sIr[4];

    const int b    = blockIdx.x;
    const int warp = threadIdx.x >> 5;
    const int lane = threadIdx.x & 31;
    const int i    = threadIdx.x;         // state index this thread owns
    const float* __restrict__ Ab = A + (size_t)b * NELEMS;

    // Early demand load: overlaps band staging + barrier.
    float dem = 0.0f;
    if (i < SN) dem = __ldg(&obs[(size_t)b * (2 * SN) + SN + i]);

    // Flattened band staging: virtual band index idx in [0, 81*19).
    // row = idx / 19 via magic, then incremental update. All 32 lanes active;
    // consecutive lanes are consecutive global addresses within a row.
    {
        int row = (threadIdx.x * 3450) >> 16;      // tid/19 for tid<1539
        int off = threadIdx.x - row * BANDW;
        #pragma unroll
        for (int k = 0; k < 13; ++k) {
            const int idx = threadIdx.x + 128 * k;
            if (idx < BAND_TOT) {
                const int e = 82 * row + off - 9;  // flat index into A
                float v = 0.0f;
                if ((unsigned)e < (unsigned)NELEMS) v = __ldg(&Ab[e]);
                band[row * BPITCH + off] = v;
            }
            off += 128 - 6 * BANDW;                // +128 slots = +6 rows, +14 off
            if (off >= BANDW) { off -= BANDW; row += 7; } else { row += 6; }
        }
    }
    __syncthreads();

    // nsc[i] = band[i][9] + (c>0)band[i-1][10] + (c<8)band[i+1][8]
    //        + (r>0)band[i-9][18] + (r<8)band[i+9][0]
    float m = 0.0f;
    if (i < SN) {
        const int r = i / GRID9;
        const int c = i - r * GRID9;
        float v = band[i * BPITCH + 9];
        if (c > 0)         v += band[(i - 1) * BPITCH + 10];
        if (c < GRID9 - 1) v += band[(i + 1) * BPITCH + 8];
        if (r > 0)         v += band[(i - GRID9) * BPITCH + 18];
        if (r < GRID9 - 1) v += band[(i + GRID9) * BPITCH + 0];
        out[(size_t)3 * B + (size_t)b * SN + i] = v;   // nsc
        m = fminf(v, dem);
    }
    #pragma unroll
    for (int off = 16; off; off >>= 1) m += __shfl_xor_sync(0xffffffffu, m, off);
    if (lane == 0) sIr[warp] = m;
    __syncthreads();
    if (threadIdx.x == 0)
        out[(size_t)B + b] = sIr[0] + sIr[1] + sIr[2] + sIr[3];    // immediate_reward
}

// ======================= Kernel 2: MLP head (batch-amortized) =======================
// Block = 256 threads = 8 warps, handles 32 batches. Warp -> 4 batches,
// lane = hidden unit, 4 register accumulators share each W-row LDS.
#define GB      32               // batches per block
#define THREADS2 256

__global__ __launch_bounds__(THREADS2)
void mlp_kernel(const float* __restrict__ W1,    // (SN, HID)
                const float* __restrict__ W2,    // (HID, HID)
                const float* __restrict__ W3,    // (HID, 1)
                const float* __restrict__ b3,
                float* __restrict__ out,         // [sym|ir|nr|nsc]
                int B)
{
    __shared__ float sW1[SN * HID];          // 10368 B
    __shared__ float sW2[HID * HID];         //  4096 B
    __shared__ float sW3[HID];
    __shared__ float sNsc[GB][SN];           // 10368 B
    __shared__ float sH1[GB][HID];           //  4096 B

    const int tid  = threadIdx.x;
    const int b0   = blockIdx.x * GB;

    for (int k = tid; k < SN * HID; k += THREADS2) sW1[k] = W1[k];
    for (int k = tid; k < HID * HID; k += THREADS2) sW2[k] = W2[k];
    if (tid < HID) sW3[tid] = W3[tid];

    // Stage nsc for 32 batches: one contiguous 2592-float region (L2-hot).
    {
        const float* __restrict__ src = out + (size_t)3 * B + (size_t)b0 * SN;
        #pragma unroll
        for (int k = 0; k < (GB * SN + THREADS2 - 1) / THREADS2; ++k) {
            const int idx = tid + THREADS2 * k;
            if (idx < GB * SN) {
                const int r = (int)(((long long)idx * 51782) >> 22);  // idx/81
                sNsc[r][idx - r * SN] = __ldg(&src[idx]);
            }
        }
    }
    __syncthreads();

    const int warp = tid >> 5;
    const int lane = tid & 31;
    const int lb   = warp * 4;               // first local batch of this warp

    // ---- h1 = relu(nsc @ W1), 4 batches per warp ----
    float a0 = 0.f, a1 = 0.f, a2 = 0.f, a3 = 0.f;
    #pragma unroll 3
    for (int i = 0; i < SN; ++i) {
        const float w = sW1[i * HID + lane];
        a0 = fmaf(sNsc[lb + 0][i], w, a0);
        a1 = fmaf(sNsc[lb + 1][i], w, a1);
        a2 = fmaf(sNsc[lb + 2][i], w, a2);
        a3 = fmaf(sNsc[lb + 3][i], w, a3);
    }
    sH1[lb + 0][lane] = fmaxf(a0, 0.f);
    sH1[lb + 1][lane] = fmaxf(a1, 0.f);
    sH1[lb + 2][lane] = fmaxf(a2, 0.f);
    sH1[lb + 3][lane] = fmaxf(a3, 0.f);
    __syncwarp();

    // ---- h2 = relu(h1 @ W2) ----
    float c0 = 0.f, c1 = 0.f, c2 = 0.f, c3 = 0.f;
    #pragma unroll
    for (int k = 0; k < HID; ++k) {
        const float w = sW2[k * HID + lane];
        c0 = fmaf(sH1[lb + 0][k], w, c0);
        c1 = fmaf(sH1[lb + 1][k], w, c1);
        c2 = fmaf(sH1[lb + 2][k], w, c2);
        c3 = fmaf(sH1[lb + 3][k], w, c3);
    }
    const float w3 = sW3[lane];
    float n0 = fmaxf(c0, 0.f) * w3;
    float n1 = fmaxf(c1, 0.f) * w3;
    float n2 = fmaxf(c2, 0.f) * w3;
    float n3 = fmaxf(c3, 0.f) * w3;
    #pragma unroll
    for (int off = 16; off; off >>= 1) {
        n0 += __shfl_xor_sync(0xffffffffu, n0, off);
        n1 += __shfl_xor_sync(0xffffffffu, n1, off);
        n2 += __shfl_xor_sync(0xffffffffu, n2, off);
        n3 += __shfl_xor_sync(0xffffffffu, n3, off);
    }

    if (lane < 4) {
        const float nr = (lane == 0 ? n0 : lane == 1 ? n1 : lane == 2 ? n2 : n3)
                       + __ldg(&b3[0]);
        const int b = b0 + lb + lane;
        const float ir = out[(size_t)B + b];     // written by nsc_kernel (L2-hot)
        out[b]                 = ir + nr;        // symbolic_val
        out[(size_t)2 * B + b] = nr;             // next_return
    }
}

extern "C" void kernel_launch(void* const* d_in, const int* in_sizes, int n_in,
                              void* d_out, int out_size)
{
    const float* obs = (const float*)d_in[0];
    const float* A   = (const float*)d_in[1];
    const float* W1  = (const float*)d_in[2];
    const float* W2  = (const float*)d_in[3];
    const float* W3  = (const float*)d_in[4];
    const float* b3  = (const float*)d_in[5];

    const int B = in_sizes[0] / (2 * SN);
    float* out = (float*)d_out;

    nsc_kernel<<<B, 128>>>(obs, A, out, B);
    mlp_kernel<<<(B + GB - 1) / GB, THREADS2>>>(W1, W2, W3, b3, out, B);
}

// round 7
// speedup vs baseline: 2.8798x; 1.0385x over previous
#include <cuda_runtime.h>

#define GRID9   9
#define SN      81
#define HID     32
#define NELEMS  (SN * SN)        // 6561
#define BANDW   19               // band offsets -9..+9 around 82j
#define BPITCH  21               // odd pitch -> conflict-free consumer reads
#define NTASK   (SN * 6)         // 486 float4 staging tasks

__global__ __launch_bounds__(128)
void gdvpn_fused(const float* __restrict__ obs,   // (B, 2*SN)
                 const float* __restrict__ A,     // (B, SN, SN)
                 const float* __restrict__ W1,    // (SN, HID)
                 const float* __restrict__ W2,    // (HID, HID)
                 const float* __restrict__ W3,    // (HID, 1)
                 const float* __restrict__ b3,
                 float* __restrict__ out,         // [sym B | ir B | nr B | nsc B*SN]
                 int B)
{
    __shared__ float band[SN * BPITCH];   // 6804 B
    __shared__ float sNsc[84];
    __shared__ float sIr[4];

    const int tid  = threadIdx.x;
    const int warp = tid >> 5;
    const int lane = tid & 31;
    const int b    = blockIdx.x;
    const long long gBatch   = (long long)b * NELEMS;
    const long long totElems = (long long)B * NELEMS;

    // Early demand load: overlaps band staging.
    float dem = 0.0f;
    if (tid < SN) dem = __ldg(&obs[(size_t)b * (2 * SN) + SN + tid]);

    // ---------- Phase 0: vectorized band staging ----------
    // Task idx -> (row j, quad q). Row j covers A-flat [82j-9, 82j+9];
    // quads are 16B-aligned in GLOBAL address space (batch base is only 4B
    // aligned, so alignment is computed on the global flat index).
    #pragma unroll
    for (int k = 0; k < 4; ++k) {
        const int idx = tid + 128 * k;
        if (idx < NTASK) {
            const int j = (idx * 10923) >> 16;      // idx / 6
            const int q = idx - 6 * j;
            const long long s_g = gBatch + 82 * j - 9;   // band origin (global)
            long long a_g = s_g & ~3LL;                  // aligned quad base
            if (a_g < 0) a_g = 0;
            const long long p = a_g + 4 * q;             // this quad's first elem
            const int off0 = (int)(p - s_g);             // band offset of p (-3..20)
            if (off0 <= 18) {
                float4 v;
                if (p + 3 < totElems) {
                    v = *reinterpret_cast<const float4*>(A + p);
                } else {                                  // tail of last batch
                    v.x = (p     < totElems) ? A[p]     : 0.f;
                    v.y = (p + 1 < totElems) ? A[p + 1] : 0.f;
                    v.z = (p + 2 < totElems) ? A[p + 2] : 0.f;
                    v.w = (p + 3 < totElems) ? A[p + 3] : 0.f;
                }
                float* br = band + j * BPITCH;
                if (off0 >= 0           ) br[off0]     = v.x;
                if ((unsigned)(off0 + 1) < BANDW) br[off0 + 1] = v.y;
                if ((unsigned)(off0 + 2) < BANDW) br[off0 + 2] = v.z;
                if ((unsigned)(off0 + 3) < BANDW) br[off0 + 3] = v.w;
            }
        }
    }
    __syncthreads();

    // ---------- Phase 1: nsc + immediate reward ----------
    // nsc[i] = band[i][9] + (c>0)band[i-1][10] + (c<8)band[i+1][8]
    //        + (r>0)band[i-9][18] + (r<8)band[i+9][0]
    float m = 0.0f;
    if (tid < SN) {
        const int i = tid;
        const int r = i / GRID9;
        const int c = i - r * GRID9;
        float v = band[i * BPITCH + 9];
        if (c > 0)         v += band[(i - 1) * BPITCH + 10];
        if (c < GRID9 - 1) v += band[(i + 1) * BPITCH + 8];
        if (r > 0)         v += band[(i - GRID9) * BPITCH + 18];
        if (r < GRID9 - 1) v += band[(i + GRID9) * BPITCH + 0];
        sNsc[i] = v;
        out[(size_t)3 * B + (size_t)b * SN + i] = v;   // nsc output
        m = fminf(v, dem);
    }
    #pragma unroll
    for (int off = 16; off; off >>= 1) m += __shfl_xor_sync(0xffffffffu, m, off);
    if (lane == 0) sIr[warp] = m;
    __syncthreads();

    // ---------- Phase 2: MLP head (warp 0 only; weights are L1-hot __ldg) ----------
    if (warp == 0) {
        float h1 = 0.0f;                        // lane owns hidden unit `lane`
        #pragma unroll 9
        for (int i = 0; i < SN; ++i)
            h1 = fmaf(sNsc[i], __ldg(&W1[i * HID + lane]), h1);
        h1 = fmaxf(h1, 0.0f);

        float h2 = 0.0f;
        #pragma unroll
        for (int k = 0; k < HID; ++k) {
            const float hk = __shfl_sync(0xffffffffu, h1, k);
            h2 = fmaf(hk, __ldg(&W2[k * HID + lane]), h2);
        }
        h2 = fmaxf(h2, 0.0f);

        float nr = h2 * __ldg(&W3[lane]);
        #pragma unroll
        for (int off = 16; off; off >>= 1) nr += __shfl_xor_sync(0xffffffffu, nr, off);

        if (lane == 0) {
            nr += __ldg(&b3[0]);
            const float ir = sIr[0] + sIr[1] + sIr[2] + sIr[3];
            out[b]                 = ir + nr;   // symbolic_val
            out[(size_t)B + b]     = ir;        // immediate_reward
            out[(size_t)2 * B + b] = nr;        // next_return
        }
    }
}

extern "C" void kernel_launch(void* const* d_in, const int* in_sizes, int n_in,
                              void* d_out, int out_size)
{
    const float* obs = (const float*)d_in[0];
    const float* A   = (const float*)d_in[1];
    const float* W1  = (const float*)d_in[2];
    const float* W2  = (const float*)d_in[3];
    const float* W3  = (const float*)d_in[4];
    const float* b3  = (const float*)d_in[5];

    const int B = in_sizes[0] / (2 * SN);
    float* out = (float*)d_out;

    gdvpn_fused<<<B, 128>>>(obs, A, W1, W2, W3, b3, out, B);
}

// round 13
// speedup vs baseline: 2.9686x; 1.0308x over previous
#include <cuda_runtime.h>

#define GRID9   9
#define SN      81
#define HID     32
#define NELEMS  (SN * SN)        // 6561
#define QPR     6                // quads per band row
#define RPITCH  24               // floats per band row (6 aligned quads)
#define NTASK   (SN * QPR)       // 486 staging tasks

__global__ __launch_bounds__(128)
void gdvpn_fused(const float* __restrict__ obs,   // (B, 2*SN)
                 const float* __restrict__ A,     // (B, SN, SN)
                 const float* __restrict__ W1,    // (SN, HID)
                 const float* __restrict__ W2,    // (HID, HID)
                 const float* __restrict__ W3,    // (HID, 1)
                 const float* __restrict__ b3,
                 float* __restrict__ out,         // [sym B | ir B | nr B | nsc B*SN]
                 int B)
{
    __shared__ float band[SN * RPITCH];   // 7776 B
    __shared__ float sNsc[84];
    __shared__ float sIr[4];
    __shared__ float sH1p[4][HID];        // h1 partials per warp

    const int tid  = threadIdx.x;
    const int warp = tid >> 5;
    const int lane = tid & 31;
    const int b    = blockIdx.x;
    const long long gBatch   = (long long)b * NELEMS;
    const long long totElems = (long long)B * NELEMS;

    // Early demand load: overlaps band staging.
    float dem = 0.0f;
    if (tid < SN) dem = __ldg(&obs[(size_t)b * (2 * SN) + SN + tid]);

    // ---------- Phase 0: aligned-quad band staging (LDG.128 -> STS.128) ----------
    // Row j's band origin s_g = gBatch + 82j - 9 (global flat). Quads are taken
    // on the GLOBAL 16B grid: a_g = s_g & ~3. Quad q is stored UNSHIFTED at
    // band[j*24 + 4q]; the consumer adds d(j) = s_g - a_g = (b + 2j + 3) & 3.
    #pragma unroll
    for (int k = 0; k < 4; ++k) {
        const int idx = tid + 128 * k;
        if (idx < NTASK) {
            const int j = (idx * 10923) >> 16;        // idx / 6
            const int q = idx - QPR * j;
            const long long s_g = gBatch + 82 * j - 9;
            const long long a_g = s_g & ~3LL;
            const long long p   = a_g + 4 * q;
            const int off0 = (int)(p - s_g);          // band offset of quad start
            if (off0 <= 18 && p >= 0) {               // quad intersects needed band
                float4 v;
                if (p + 3 < totElems) {
                    v = *reinterpret_cast<const float4*>(A + p);
                } else {                               // tail of the last batch
                    v.x = (p     < totElems) ? __ldg(&A[p])     : 0.f;
                    v.y = (p + 1 < totElems) ? __ldg(&A[p + 1]) : 0.f;
                    v.z = (p + 2 < totElems) ? __ldg(&A[p + 2]) : 0.f;
                    v.w = (p + 3 < totElems) ? __ldg(&A[p + 3]) : 0.f;
                }
                *reinterpret_cast<float4*>(band + j * RPITCH + 4 * q) = v;
            }
        }
    }
    __syncthreads();

    // ---------- Phase 1: nsc + immediate reward ----------
    // value(j, k) = band[j*24 + d(j) + k],  d(j) = (b + 2j + 3) & 3
    // nsc[i] = v(i,9) + (c>0)v(i-1,10) + (c<8)v(i+1,8) + (r>0)v(i-9,18) + (r<8)v(i+9,0)
    float m = 0.0f;
    if (tid < SN) {
        const int i = tid;
        const int r = i / GRID9;
        const int c = i - r * GRID9;
        auto BV = [&](int j, int k) -> float {
            return band[j * RPITCH + ((b + 2 * j + 3) & 3) + k];
        };
        float v = BV(i, 9);
        if (c > 0)         v += BV(i - 1, 10);
        if (c < GRID9 - 1) v += BV(i + 1, 8);
        if (r > 0)         v += BV(i - GRID9, 18);
        if (r < GRID9 - 1) v += BV(i + GRID9, 0);
        sNsc[i] = v;
        out[(size_t)3 * B + (size_t)b * SN + i] = v;   // nsc output
        m = fminf(v, dem);
    }
    #pragma unroll
    for (int off = 16; off; off >>= 1) m += __shfl_xor_sync(0xffffffffu, m, off);
    if (lane == 0) sIr[warp] = m;
    __syncthreads();

    // ---------- Phase 2a: h1 partials, all 4 warps (W1 rows are L1-hot) ----------
    {
        const int i0 = warp * 20;
        const int i1 = (warp == 3) ? SN : i0 + 20;
        float acc = 0.0f;
        #pragma unroll 5
        for (int i = i0; i < i1; ++i)
            acc = fmaf(sNsc[i], __ldg(&W1[i * HID + lane]), acc);
        sH1p[warp][lane] = acc;
    }
    __syncthreads();

    // ---------- Phase 2b: finish MLP in warp 0 ----------
    if (warp == 0) {
        float h1 = sH1p[0][lane] + sH1p[1][lane] + sH1p[2][lane] + sH1p[3][lane];
        h1 = fmaxf(h1, 0.0f);

        float h2 = 0.0f;
        #pragma unroll
        for (int k = 0; k < HID; ++k) {
            const float hk = __shfl_sync(0xffffffffu, h1, k);
            h2 = fmaf(hk, __ldg(&W2[k * HID + lane]), h2);
        }
        h2 = fmaxf(h2, 0.0f);

        float nr = h2 * __ldg(&W3[lane]);
        #pragma unroll
        for (int off = 16; off; off >>= 1) nr += __shfl_xor_sync(0xffffffffu, nr, off);

        if (lane == 0) {
            nr += __ldg(&b3[0]);
            const float ir = sIr[0] + sIr[1] + sIr[2] + sIr[3];
            out[b]                 = ir + nr;   // symbolic_val
            out[(size_t)B + b]     = ir;        // immediate_reward
            out[(size_t)2 * B + b] = nr;        // next_return
        }
    }
}

extern "C" void kernel_launch(void* const* d_in, const int* in_sizes, int n_in,
                              void* d_out, int out_size)
{
    const float* obs = (const float*)d_in[0];
    const float* A   = (const float*)d_in[1];
    const float* W1  = (const float*)d_in[2];
    const float* W2  = (const float*)d_in[3];
    const float* W3  = (const float*)d_in[4];
    const float* b3  = (const float*)d_in[5];

    const int B = in_sizes[0] / (2 * SN);
    float* out = (float*)d_out;

    gdvpn_fused<<<B, 128>>>(obs, A, W1, W2, W3, b3, out, B);
}